// round 14
// baseline (speedup 1.0000x reference)
#include <cuda_runtime.h>
#include <cuda_fp16.h>
#include <cstdint>

// out[8192,1024] = x[8192,1024] @ W[1024,1024]^T, fp32 accuracy.
// Single fp16 GEMM, K=1024. rel_err 2.937e-4 (measured, gate 1e-3).
// R13 profile: tensor 62.8%, occ 16.6% -> latency-bound, NOT at HMMA ceiling.
// This round: 8 warps/CTA (32x32 warp tiles), 3 CTAs/SM -> 24 warps/SM
// (37.5% occ) to cover the per-kt sync windows that drain the tensor pipe.

#define BATCHN 8192
#define INF    1024
#define OUTF   1024
#define KBIG   1024
#define BM 128
#define BN 64
#define BK 64
#define KTILES 16          // 1024/64
#define NSTAGE 3
#define ATILE  16384       // 128 x 64 fp16
#define BTILE  8192        //  64 x 64 fp16
#define MTILES 64
#define NTILES 16
#define THREADS 256
#define SMEM_TOTAL (NSTAGE * (ATILE + BTILE))   // 72 KB

__device__ __align__(128) unsigned char g_Abuf[(size_t)BATCHN * KBIG * 2]; // 16 MB
__device__ __align__(128) unsigned char g_Bbuf[(size_t)OUTF  * KBIG * 2]; //  2 MB

// ---------------------------------------------------------------------------
// Fused fp32 -> fp16 conversion (unchanged from 58.3us champion).
// ---------------------------------------------------------------------------
__global__ void qnl_convert(const float* __restrict__ x, const float* __restrict__ w) {
    const uint32_t bid = blockIdx.x;
    const uint32_t tid = threadIdx.x;
    if (bid < 1024) {
        uint32_t idx = bid * 256 + tid;
        uint32_t b = idx >> 7;             // row in [0,2048)
        uint32_t c = idx & 127;            // 8-elem chunk
        float4 v[8];
#pragma unroll
        for (int r = 0; r < 4; r++) {
            const float4* p = reinterpret_cast<const float4*>(
                x + (((size_t)b + r * 2048) << 10) + (c << 3));
            v[2 * r]     = p[0];
            v[2 * r + 1] = p[1];
        }
#pragma unroll
        for (int r = 0; r < 4; r++) {
            float vs[8] = {v[2*r].x, v[2*r].y, v[2*r].z, v[2*r].w,
                           v[2*r+1].x, v[2*r+1].y, v[2*r+1].z, v[2*r+1].w};
            __align__(16) __half h[8];
#pragma unroll
            for (int j = 0; j < 8; j++) h[j] = __float2half(vs[j]);
            *reinterpret_cast<uint4*>(
                g_Abuf + ((size_t)b + r * 2048) * (KBIG * 2) + (c << 4)) =
                *reinterpret_cast<uint4*>(h);
        }
    } else {
        uint32_t idx = (bid - 1024) * 256 + tid;
        uint32_t o = idx >> 7;
        uint32_t c = idx & 127;
        const float4* wp = reinterpret_cast<const float4*>(w + ((size_t)o << 10) + (c << 3));
        float4 v0 = wp[0], v1 = wp[1];
        float vs[8] = {v0.x, v0.y, v0.z, v0.w, v1.x, v1.y, v1.z, v1.w};
        __align__(16) __half h[8];
#pragma unroll
        for (int j = 0; j < 8; j++) h[j] = __float2half(vs[j]);
        *reinterpret_cast<uint4*>(g_Bbuf + (size_t)o * (KBIG * 2) + (c << 4)) =
            *reinterpret_cast<uint4*>(h);
    }
}

// ---------------------------------------------------------------------------
// GEMM: cp.async 3-stage + ldmatrix + mma.sync.m16n8k16, 32x32 warp tiles,
// 8 warps/CTA, 3 CTAs/SM.
// ---------------------------------------------------------------------------
__device__ __forceinline__ void cp16(uint32_t saddr, const void* gaddr) {
    asm volatile("cp.async.cg.shared.global [%0], [%1], 16;"
                 :: "r"(saddr), "l"(gaddr));
}
__device__ __forceinline__ void cp_commit() {
    asm volatile("cp.async.commit_group;");
}
__device__ __forceinline__ void cp_wait1() {
    asm volatile("cp.async.wait_group %0;" :: "n"(NSTAGE - 2));
}

__device__ __forceinline__ void ldsm_x4(uint32_t& r0, uint32_t& r1, uint32_t& r2, uint32_t& r3,
                                        uint32_t addr) {
    asm volatile("ldmatrix.sync.aligned.m8n8.x4.shared.b16 {%0,%1,%2,%3}, [%4];"
                 : "=r"(r0), "=r"(r1), "=r"(r2), "=r"(r3) : "r"(addr));
}
__device__ __forceinline__ void mma16816(float* c, const uint32_t* a, const uint32_t* b) {
    asm volatile(
        "mma.sync.aligned.m16n8k16.row.col.f32.f16.f16.f32 "
        "{%0,%1,%2,%3}, {%4,%5,%6,%7}, {%8,%9}, {%0,%1,%2,%3};"
        : "+f"(c[0]), "+f"(c[1]), "+f"(c[2]), "+f"(c[3])
        : "r"(a[0]), "r"(a[1]), "r"(a[2]), "r"(a[3]), "r"(b[0]), "r"(b[1]));
}

__global__ void __launch_bounds__(THREADS, 3) qnl_gemm(float* __restrict__ out) {
    extern __shared__ __align__(128) unsigned char smem[];
    const uint32_t sA = (uint32_t)__cvta_generic_to_shared(smem);
    const uint32_t sB = sA + NSTAGE * ATILE;

    const int tid = threadIdx.x;
    const int lane = tid & 31;
    const int wid = tid >> 5;          // 8 warps
    const int wm = wid & 3;            // warp grid 4 (M) x 2 (N), 32x32 tiles
    const int wn = wid >> 2;
    const uint32_t mt = blockIdx.x >> 4;
    const uint32_t nt = blockIdx.x & 15;

    const unsigned char* gA = g_Abuf + (size_t)(mt * BM) * (KBIG * 2);
    const unsigned char* gB = g_Bbuf + (size_t)(nt * BN) * (KBIG * 2);

    // Per-thread load slots: A 4 x 16B, B 2 x 16B per stage (256 thr).
    uint32_t ldRowA[4], ldSwA[4];
#pragma unroll
    for (int t = 0; t < 4; t++) {
        uint32_t cid = tid + t * THREADS;  // 0..1023
        uint32_t row = cid >> 3, cc = cid & 7;
        ldRowA[t] = row;
        ldSwA[t] = row * 128 + ((cc ^ (row & 7)) * 16);
    }
    uint32_t ldRowB[2], ldSwB[2];
#pragma unroll
    for (int t = 0; t < 2; t++) {
        uint32_t cid = tid + t * THREADS;  // 0..511
        uint32_t row = cid >> 3, cc = cid & 7;
        ldRowB[t] = row;
        ldSwB[t] = row * 128 + ((cc ^ (row & 7)) * 16);
    }

    auto load_stage = [&](int stage, int kt) {
#pragma unroll
        for (int t = 0; t < 4; t++) {
            uint32_t cc = (tid + t * THREADS) & 7;
            cp16(sA + stage * ATILE + ldSwA[t],
                 gA + (size_t)ldRowA[t] * (KBIG * 2) + kt * 128 + cc * 16);
        }
#pragma unroll
        for (int t = 0; t < 2; t++) {
            uint32_t cc = (tid + t * THREADS) & 7;
            cp16(sB + stage * BTILE + ldSwB[t],
                 gB + (size_t)ldRowB[t] * (KBIG * 2) + kt * 128 + cc * 16);
        }
        cp_commit();
    };

    // A ldmatrix addressing (x4: 16 rows x 2 k-halves), 2 m-frags of 16.
    const uint32_t aRel = lane & 15;
    const uint32_t aHalf = lane >> 4;
    uint32_t aRowByte[2];
#pragma unroll
    for (int mf = 0; mf < 2; mf++)
        aRowByte[mf] = (wm * 32 + mf * 16 + aRel) * 128;

    // B ldmatrix addressing (x4: two 8-row n-blocks x two k-halves).
    const uint32_t bRow8 = lane & 7;
    const uint32_t bHalf = (lane >> 3) & 1;
    const uint32_t bSel  = lane >> 4;
    uint32_t bRowByte[2];
#pragma unroll
    for (int j = 0; j < 2; j++)
        bRowByte[j] = (wn * 32 + j * 16 + bSel * 8 + bRow8) * 128;

    float acc[2][4][4];
#pragma unroll
    for (int mf = 0; mf < 2; mf++)
#pragma unroll
        for (int nf = 0; nf < 4; nf++)
#pragma unroll
            for (int v = 0; v < 4; v++) acc[mf][nf][v] = 0.0f;

    // Double-buffered fragments.
    uint32_t af[2][2][4], bf[2][4][2];

    // Prologue: fill NSTAGE-1 stages.
#pragma unroll
    for (int s = 0; s < NSTAGE - 1; s++) load_stage(s, s);

    int stage = 0;
    for (int kt = 0; kt < KTILES; kt++) {
        cp_wait1();
        __syncthreads();

        const uint32_t aBase = sA + stage * ATILE;
        const uint32_t bBase = sB + stage * BTILE;

        // Load ks=0 fragments into buffer 0.
        {
            const uint32_t aChunk = ((0 + aHalf) ^ (aRel & 7)) * 16;
            const uint32_t bChunk = ((0 + bHalf) ^ bRow8) * 16;
#pragma unroll
            for (int mf = 0; mf < 2; mf++)
                ldsm_x4(af[0][mf][0], af[0][mf][1], af[0][mf][2], af[0][mf][3],
                        aBase + aRowByte[mf] + aChunk);
#pragma unroll
            for (int j = 0; j < 2; j++)
                ldsm_x4(bf[0][2 * j][0], bf[0][2 * j][1],
                        bf[0][2 * j + 1][0], bf[0][2 * j + 1][1],
                        bBase + bRowByte[j] + bChunk);
        }

        // Issue next stage's cp.async while ldmatrix latency drains.
        int nxt = kt + NSTAGE - 1;
        if (nxt < KTILES) load_stage((stage + NSTAGE - 1) % NSTAGE, nxt);
        else cp_commit();   // keep group count consistent

#pragma unroll
        for (int ks = 0; ks < 4; ks++) {
            const int cur = ks & 1;
            if (ks < 3) {
                const int nb = (ks + 1) & 1;
                const uint32_t aChunk = (((ks + 1) * 2 + aHalf) ^ (aRel & 7)) * 16;
                const uint32_t bChunk = (((ks + 1) * 2 + bHalf) ^ bRow8) * 16;
#pragma unroll
                for (int mf = 0; mf < 2; mf++)
                    ldsm_x4(af[nb][mf][0], af[nb][mf][1], af[nb][mf][2], af[nb][mf][3],
                            aBase + aRowByte[mf] + aChunk);
#pragma unroll
                for (int j = 0; j < 2; j++)
                    ldsm_x4(bf[nb][2 * j][0], bf[nb][2 * j][1],
                            bf[nb][2 * j + 1][0], bf[nb][2 * j + 1][1],
                            bBase + bRowByte[j] + bChunk);
            }
#pragma unroll
            for (int mf = 0; mf < 2; mf++)
#pragma unroll
                for (int nf = 0; nf < 4; nf++)
                    mma16816(acc[mf][nf], af[cur][mf], bf[cur][nf]);
        }
        stage = (stage + 1 == NSTAGE) ? 0 : stage + 1;
    }

    // Epilogue: direct stores (c0,c1 row g; c2,c3 row g+8).
    const int gid = lane >> 2, tig = lane & 3;
    const uint32_t rBase = mt * BM + wm * 32 + gid;
    const uint32_t cBase = nt * BN + wn * 32 + tig * 2;
#pragma unroll
    for (int mf = 0; mf < 2; mf++) {
#pragma unroll
        for (int nf = 0; nf < 4; nf++) {
            float* p0 = out + (size_t)(rBase + mf * 16) * OUTF + cBase + nf * 8;
            float* p1 = p0 + 8 * OUTF;
            *reinterpret_cast<float2*>(p0) = make_float2(acc[mf][nf][0], acc[mf][nf][1]);
            *reinterpret_cast<float2*>(p1) = make_float2(acc[mf][nf][2], acc[mf][nf][3]);
        }
    }
}

// ---------------------------------------------------------------------------
extern "C" void kernel_launch(void* const* d_in, const int* in_sizes, int n_in,
                              void* d_out, int out_size) {
    const float* x = (const float*)d_in[0];   // [8192,1024] fp32
    const float* w = (const float*)d_in[1];   // [1024,1024] fp32
    // d_in[2] (bias) cancels exactly in the reference value path.
    (void)in_sizes; (void)n_in; (void)out_size;

    static bool attr_set = false;
    if (!attr_set) {
        cudaFuncSetAttribute(qnl_gemm, cudaFuncAttributeMaxDynamicSharedMemorySize, SMEM_TOTAL);
        attr_set = true;
    }

    qnl_convert<<<1536, 256>>>(x, w);
    qnl_gemm<<<MTILES * NTILES, THREADS, SMEM_TOTAL>>>((float*)d_out);
}

// round 16
// speedup vs baseline: 1.1487x; 1.1487x over previous
#include <cuda_runtime.h>
#include <cuda_fp16.h>
#include <cstdint>

// out[8192,1024] = x[8192,1024] @ W[1024,1024]^T, fp32 accuracy.
// Single fp16 GEMM, K=1024. rel_err 2.937e-4 (measured, gate 1e-3).
// R13 champion shape (128x64 CTA, 4 warps of 64x32, 3 CTA/SM) +
// cross-kt fragment pipelining (ks0 LDSM of stage kt+1 issued before the
// final MMA block of kt). R15's stage-index bug ((s+2) mod 3 computed
// wrongly for s=2) fixed with explicit wrap arithmetic.

#define BATCHN 8192
#define INF    1024
#define OUTF   1024
#define KBIG   1024
#define BM 128
#define BN 64
#define BK 64
#define KTILES 16          // 1024/64
#define NSTAGE 3
#define ATILE  16384       // 128 x 64 fp16
#define BTILE  8192        //  64 x 64 fp16
#define MTILES 64
#define NTILES 16
#define SMEM_TOTAL (NSTAGE * (ATILE + BTILE))   // 72 KB

__device__ __align__(128) unsigned char g_Abuf[(size_t)BATCHN * KBIG * 2]; // 16 MB
__device__ __align__(128) unsigned char g_Bbuf[(size_t)OUTF  * KBIG * 2]; //  2 MB

// ---------------------------------------------------------------------------
// Fused fp32 -> fp16 conversion (unchanged from 58.3us champion).
// ---------------------------------------------------------------------------
__global__ void qnl_convert(const float* __restrict__ x, const float* __restrict__ w) {
    const uint32_t bid = blockIdx.x;
    const uint32_t tid = threadIdx.x;
    if (bid < 1024) {
        uint32_t idx = bid * 256 + tid;
        uint32_t b = idx >> 7;             // row in [0,2048)
        uint32_t c = idx & 127;            // 8-elem chunk
        float4 v[8];
#pragma unroll
        for (int r = 0; r < 4; r++) {
            const float4* p = reinterpret_cast<const float4*>(
                x + (((size_t)b + r * 2048) << 10) + (c << 3));
            v[2 * r]     = p[0];
            v[2 * r + 1] = p[1];
        }
#pragma unroll
        for (int r = 0; r < 4; r++) {
            float vs[8] = {v[2*r].x, v[2*r].y, v[2*r].z, v[2*r].w,
                           v[2*r+1].x, v[2*r+1].y, v[2*r+1].z, v[2*r+1].w};
            __align__(16) __half h[8];
#pragma unroll
            for (int j = 0; j < 8; j++) h[j] = __float2half(vs[j]);
            *reinterpret_cast<uint4*>(
                g_Abuf + ((size_t)b + r * 2048) * (KBIG * 2) + (c << 4)) =
                *reinterpret_cast<uint4*>(h);
        }
    } else {
        uint32_t idx = (bid - 1024) * 256 + tid;
        uint32_t o = idx >> 7;
        uint32_t c = idx & 127;
        const float4* wp = reinterpret_cast<const float4*>(w + ((size_t)o << 10) + (c << 3));
        float4 v0 = wp[0], v1 = wp[1];
        float vs[8] = {v0.x, v0.y, v0.z, v0.w, v1.x, v1.y, v1.z, v1.w};
        __align__(16) __half h[8];
#pragma unroll
        for (int j = 0; j < 8; j++) h[j] = __float2half(vs[j]);
        *reinterpret_cast<uint4*>(g_Bbuf + (size_t)o * (KBIG * 2) + (c << 4)) =
            *reinterpret_cast<uint4*>(h);
    }
}

// ---------------------------------------------------------------------------
// GEMM helpers.
// ---------------------------------------------------------------------------
__device__ __forceinline__ void cp16(uint32_t saddr, const void* gaddr) {
    asm volatile("cp.async.cg.shared.global [%0], [%1], 16;"
                 :: "r"(saddr), "l"(gaddr));
}
__device__ __forceinline__ void cp_commit() {
    asm volatile("cp.async.commit_group;");
}
__device__ __forceinline__ void cp_wait1() {
    asm volatile("cp.async.wait_group %0;" :: "n"(NSTAGE - 2));
}

__device__ __forceinline__ void ldsm_x4(uint32_t& r0, uint32_t& r1, uint32_t& r2, uint32_t& r3,
                                        uint32_t addr) {
    asm volatile("ldmatrix.sync.aligned.m8n8.x4.shared.b16 {%0,%1,%2,%3}, [%4];"
                 : "=r"(r0), "=r"(r1), "=r"(r2), "=r"(r3) : "r"(addr));
}
__device__ __forceinline__ void mma16816(float* c, const uint32_t* a, const uint32_t* b) {
    asm volatile(
        "mma.sync.aligned.m16n8k16.row.col.f32.f16.f16.f32 "
        "{%0,%1,%2,%3}, {%4,%5,%6,%7}, {%8,%9}, {%0,%1,%2,%3};"
        : "+f"(c[0]), "+f"(c[1]), "+f"(c[2]), "+f"(c[3])
        : "r"(a[0]), "r"(a[1]), "r"(a[2]), "r"(a[3]), "r"(b[0]), "r"(b[1]));
}

__global__ void __launch_bounds__(128, 3) qnl_gemm(float* __restrict__ out) {
    extern __shared__ __align__(128) unsigned char smem[];
    const uint32_t sA = (uint32_t)__cvta_generic_to_shared(smem);
    const uint32_t sB = sA + NSTAGE * ATILE;

    const int tid = threadIdx.x;
    const int lane = tid & 31;
    const int wid = tid >> 5;          // 4 warps
    const int wm = wid & 1;            // warp grid 2 (M) x 2 (N), 64x32 tiles
    const int wn = wid >> 1;
    const uint32_t mt = blockIdx.x >> 4;
    const uint32_t nt = blockIdx.x & 15;

    const unsigned char* gA = g_Abuf + (size_t)(mt * BM) * (KBIG * 2);
    const unsigned char* gB = g_Bbuf + (size_t)(nt * BN) * (KBIG * 2);

    // Per-thread load slots: A 8 x 16B, B 4 x 16B per stage (128 thr).
    uint32_t ldRowA[8], ldSwA[8];
#pragma unroll
    for (int t = 0; t < 8; t++) {
        uint32_t cid = tid + t * 128;
        uint32_t row = cid >> 3, cc = cid & 7;
        ldRowA[t] = row;
        ldSwA[t] = row * 128 + ((cc ^ (row & 7)) * 16);
    }
    uint32_t ldRowB[4], ldSwB[4];
#pragma unroll
    for (int t = 0; t < 4; t++) {
        uint32_t cid = tid + t * 128;
        uint32_t row = cid >> 3, cc = cid & 7;
        ldRowB[t] = row;
        ldSwB[t] = row * 128 + ((cc ^ (row & 7)) * 16);
    }

    auto load_stage = [&](int stage, int kt) {
#pragma unroll
        for (int t = 0; t < 8; t++) {
            uint32_t cc = (tid + t * 128) & 7;
            cp16(sA + stage * ATILE + ldSwA[t],
                 gA + (size_t)ldRowA[t] * (KBIG * 2) + kt * 128 + cc * 16);
        }
#pragma unroll
        for (int t = 0; t < 4; t++) {
            uint32_t cc = (tid + t * 128) & 7;
            cp16(sB + stage * BTILE + ldSwB[t],
                 gB + (size_t)ldRowB[t] * (KBIG * 2) + kt * 128 + cc * 16);
        }
        cp_commit();
    };

    // ldmatrix addressing.
    const uint32_t aRel = lane & 15;
    const uint32_t aHalf = lane >> 4;
    uint32_t aRowByte[4];
#pragma unroll
    for (int mf = 0; mf < 4; mf++)
        aRowByte[mf] = (wm * 64 + mf * 16 + aRel) * 128;

    const uint32_t bRow8 = lane & 7;
    const uint32_t bHalf = (lane >> 3) & 1;
    const uint32_t bSel  = lane >> 4;
    uint32_t bRowByte[2];
#pragma unroll
    for (int j = 0; j < 2; j++)
        bRowByte[j] = (wn * 32 + j * 16 + bSel * 8 + bRow8) * 128;

    float acc[4][4][4];
#pragma unroll
    for (int mf = 0; mf < 4; mf++)
#pragma unroll
        for (int nf = 0; nf < 4; nf++)
#pragma unroll
            for (int v = 0; v < 4; v++) acc[mf][nf][v] = 0.0f;

    uint32_t af[2][4][4], bf[2][4][2];

    // Fragment loader: buf (0/1), stage bases, ks index (0..3).
    auto load_frags = [&](int buf, uint32_t aBase, uint32_t bBase, int ks) {
        const uint32_t aChunk = ((ks * 2 + aHalf) ^ (aRel & 7)) * 16;
        const uint32_t bChunk = ((ks * 2 + bHalf) ^ bRow8) * 16;
#pragma unroll
        for (int mf = 0; mf < 4; mf++)
            ldsm_x4(af[buf][mf][0], af[buf][mf][1], af[buf][mf][2], af[buf][mf][3],
                    aBase + aRowByte[mf] + aChunk);
#pragma unroll
        for (int j = 0; j < 2; j++)
            ldsm_x4(bf[buf][2 * j][0], bf[buf][2 * j][1],
                    bf[buf][2 * j + 1][0], bf[buf][2 * j + 1][1],
                    bBase + bRowByte[j] + bChunk);
    };
    auto mma_block = [&](int buf) {
#pragma unroll
        for (int mf = 0; mf < 4; mf++)
#pragma unroll
            for (int nf = 0; nf < 4; nf++)
                mma16816(acc[mf][nf], af[buf][mf], bf[buf][nf]);
    };

    // Prologue: stages 0,1 in flight; frags ks0 of stage 0 resident.
    load_stage(0, 0);
    load_stage(1, 1);
    cp_wait1();
    __syncthreads();
    load_frags(0, sA, sB, 0);

    int stage = 0;
    for (int kt = 0; kt < KTILES; kt++) {
        const uint32_t aBase = sA + stage * ATILE;
        const uint32_t bBase = sB + stage * BTILE;

        // ks = 0..2: load next frag buffer, mma current.
#pragma unroll
        for (int ks = 0; ks < 3; ks++) {
            load_frags((ks + 1) & 1, aBase, bBase, ks + 1);
            mma_block(ks & 1);
        }

        // ks = 3 boundary: issue cp for stage kt+2, wait for stage kt+1,
        // sync, preload next ks0 frags, THEN final mma (hides LDSM latency).
        const int nstage = (stage + 1 == NSTAGE) ? 0 : stage + 1;
        const int lstage = (stage + 2 >= NSTAGE) ? stage + 2 - NSTAGE : stage + 2;
        if (kt + 2 < KTILES) load_stage(lstage, kt + 2);
        else cp_commit();   // keep group count consistent
        cp_wait1();
        __syncthreads();
        if (kt + 1 < KTILES)
            load_frags(0, sA + nstage * ATILE, sB + nstage * BTILE, 0);
        mma_block(1);
        stage = nstage;
    }

    // Epilogue: direct stores (c0,c1 row g; c2,c3 row g+8).
    const int gid = lane >> 2, tig = lane & 3;
    const uint32_t rBase = mt * BM + wm * 64 + gid;
    const uint32_t cBase = nt * BN + wn * 32 + tig * 2;
#pragma unroll
    for (int mf = 0; mf < 4; mf++) {
#pragma unroll
        for (int nf = 0; nf < 4; nf++) {
            float* p0 = out + (size_t)(rBase + mf * 16) * OUTF + cBase + nf * 8;
            float* p1 = p0 + 8 * OUTF;
            *reinterpret_cast<float2*>(p0) = make_float2(acc[mf][nf][0], acc[mf][nf][1]);
            *reinterpret_cast<float2*>(p1) = make_float2(acc[mf][nf][2], acc[mf][nf][3]);
        }
    }
}

// ---------------------------------------------------------------------------
extern "C" void kernel_launch(void* const* d_in, const int* in_sizes, int n_in,
                              void* d_out, int out_size) {
    const float* x = (const float*)d_in[0];   // [8192,1024] fp32
    const float* w = (const float*)d_in[1];   // [1024,1024] fp32
    // d_in[2] (bias) cancels exactly in the reference value path.
    (void)in_sizes; (void)n_in; (void)out_size;

    static bool attr_set = false;
    if (!attr_set) {
        cudaFuncSetAttribute(qnl_gemm, cudaFuncAttributeMaxDynamicSharedMemorySize, SMEM_TOTAL);
        attr_set = true;
    }

    qnl_convert<<<1536, 256>>>(x, w);
    qnl_gemm<<<MTILES * NTILES, 128, SMEM_TOTAL>>>((float*)d_out);
}